// round 13
// baseline (speedup 1.0000x reference)
#include <cuda_runtime.h>
#include <cuda_fp16.h>
#include <cstdint>
#include <math.h>

// ---------------------------------------------------------------------------
// GRU cell, legacy mma path (tcgen05 rejected by harness PTX target sm_103).
// R13: single PERSISTENT kernel, ticket-scheduled. 296 CTAs (<=1 wave) pull
// tiles from a global counter: per row panel, 24 phase-1 tiles (r/z/hp gates)
// interleaved with 8 phase-2 tiles of panel (p-LAG). Per-panel completion
// flags (24 producers) gate phase-2 via threadfence release/acquire.
// Monotonic tickets => producers always precede consumers => deadlock-free.
// Mainloop = exact R12 (128x128 CTA tile, 8 warps 64x32, BK=64, NST=3,
// fp16 ldmatrix+mma, 2 CTA/SM). Kills wave tails + phase boundary.
// ---------------------------------------------------------------------------

#define BATCH   16384
#define HID     1024
#define KCAT    2048
#define BK      64            // k halves per stage (4 x k16 MMA steps)
#define NST     3

#define BM 128
#define BN 128
#define RS 72                               // smem row stride in halves (144 B)
#define A_STAGE_B (BM * RS * 2)             // 18432 B
#define B_STAGE_B (BN * RS * 2)             // 18432 B
#define STAGE_B   (A_STAGE_B + B_STAGE_B)   // 36864 B
#define SMEM_TOTAL (NST * STAGE_B)          // 110592 B (x2 CTAs <= 228 KB)

#define NPANEL 128            // row panels of 128
#define LAG    12             // phase-2 panel lag (producers long finished)
#define T_MAIN (NPANEL * 32)                 // 4096 (24 p1 + 8 p2-slots / panel)
#define T_TOT  (T_MAIN + 8 * LAG)            // tail phase-2 for last LAG panels
#define NCTA   296            // 148 SMs x 2 CTAs

// -------------------------- device scratch ---------------------------------
__device__ __half g_A [BATCH * KCAT];
__device__ __half g_Wt[3][HID * KCAT];   // [n][k]
__device__ __half g_rh[BATCH * HID];
__device__ __half g_z [BATCH * HID];
__device__ __half g_hp[BATCH * HID];
__device__ unsigned g_ticket;
__device__ unsigned g_flag[NPANEL];

// -------------------------- helpers ----------------------------------------
__device__ __forceinline__ void mma_f16(float* c, const uint32_t* a, const uint32_t* b) {
    asm volatile(
        "mma.sync.aligned.m16n8k16.row.col.f32.f16.f16.f32 "
        "{%0,%1,%2,%3}, {%4,%5,%6,%7}, {%8,%9}, {%0,%1,%2,%3};\n"
        : "+f"(c[0]), "+f"(c[1]), "+f"(c[2]), "+f"(c[3])
        : "r"(a[0]), "r"(a[1]), "r"(a[2]), "r"(a[3]),
          "r"(b[0]), "r"(b[1]));
}
__device__ __forceinline__ void ldsm4(uint32_t* r, uint32_t addr) {
    asm volatile("ldmatrix.sync.aligned.m8n8.x4.shared.b16 {%0,%1,%2,%3}, [%4];"
                 : "=r"(r[0]), "=r"(r[1]), "=r"(r[2]), "=r"(r[3]) : "r"(addr));
}
__device__ __forceinline__ void cp16u(uint32_t smem_dst, const void* gmem_src) {
    asm volatile("cp.async.cg.shared.global [%0], [%1], 16;" :: "r"(smem_dst), "l"(gmem_src));
}
__device__ __forceinline__ void cp_commit() { asm volatile("cp.async.commit_group;"); }
template <int N>
__device__ __forceinline__ void cp_wait() { asm volatile("cp.async.wait_group %0;" :: "n"(N) : "memory"); }
__device__ __forceinline__ float sigmoidf_fast(float v) { return 1.0f / (1.0f + __expf(-v)); }
__device__ __forceinline__ float tanhf_fast(float v) {
    return 1.0f - 2.0f / (__expf(2.0f * v) + 1.0f);
}

// ---------------------------------------------------------------------------
// Init + prep kernels
// ---------------------------------------------------------------------------
__global__ void init_kernel() {
    if (threadIdx.x == 0) g_ticket = 0;
    if (threadIdx.x < NPANEL) g_flag[threadIdx.x] = 0;
}

__global__ void prep_concat_kernel(const float* __restrict__ h,
                                   const float* __restrict__ x)
{
    size_t n8 = (size_t)BATCH * KCAT / 8;
    for (size_t i = (size_t)blockIdx.x * blockDim.x + threadIdx.x;
         i < n8; i += (size_t)gridDim.x * blockDim.x) {
        size_t e   = i * 8;
        size_t row = e >> 11;
        size_t col = e & (KCAT - 1);
        const float* src = (col < HID) ? (h + row * HID + col)
                                       : (x + row * HID + (col - HID));
        float4 v0 = ((const float4*)src)[0];
        float4 v1 = ((const float4*)src)[1];
        __half2 o[4];
        o[0] = __float22half2_rn(make_float2(v0.x, v0.y));
        o[1] = __float22half2_rn(make_float2(v0.z, v0.w));
        o[2] = __float22half2_rn(make_float2(v1.x, v1.y));
        o[3] = __float22half2_rn(make_float2(v1.z, v1.w));
        ((uint4*)g_A)[i] = *(uint4*)o;
    }
}

__global__ void prep_weights_kernel(const float* __restrict__ Wr,
                                    const float* __restrict__ Wz,
                                    const float* __restrict__ Wh)
{
    __shared__ float t[32][33];
    const float* src = (blockIdx.z == 0) ? Wr : (blockIdx.z == 1) ? Wz : Wh;
    __half* dst = g_Wt[blockIdx.z];
    int tx = threadIdx.x, ty = threadIdx.y;
    int c0 = blockIdx.x * 32;   // n
    int r0 = blockIdx.y * 32;   // k
    #pragma unroll
    for (int j = 0; j < 32; j += 8)
        t[ty + j][tx] = src[(size_t)(r0 + ty + j) * HID + c0 + tx];
    __syncthreads();
    #pragma unroll
    for (int j = 0; j < 32; j += 8)
        dst[(size_t)(c0 + ty + j) * KCAT + r0 + tx] = __float2half_rn(t[tx][ty + j]);
}

// ---------------------------------------------------------------------------
// Persistent fused GEMM kernel.
// ---------------------------------------------------------------------------
__global__ void __launch_bounds__(256, 2)
gru_fused(const float* __restrict__ h, float* __restrict__ out)
{
    extern __shared__ char smem[];
    __shared__ unsigned s_ticket;
    const uint32_t sbase = (uint32_t)__cvta_generic_to_shared(smem);
    const int tid    = threadIdx.x;
    const int lane   = tid & 31;
    const int wid    = tid >> 5;
    const int warp_m = wid >> 2;         // 0..1 -> 64-row band
    const int warp_n = wid & 3;          // 0..3 -> 32-col band

    // per-thread ldmatrix base offsets (bytes within stage) — tile-invariant
    uint32_t a_off[4];
    #pragma unroll
    for (int mt = 0; mt < 4; mt++)
        a_off[mt] = (warp_m * 64 + mt * 16 + (lane & 15)) * (RS * 2)
                  + ((lane >> 4) & 1) * 16;
    uint32_t b_off[2];
    #pragma unroll
    for (int nt2 = 0; nt2 < 2; nt2++)
        b_off[nt2] = A_STAGE_B
                   + (warp_n * 32 + nt2 * 16 + (lane & 7) + ((lane >> 4) & 1) * 8) * (RS * 2)
                   + ((lane >> 3) & 1) * 16;

    for (;;) {
        if (tid == 0) s_ticket = atomicAdd(&g_ticket, 1u);
        __syncthreads();
        const unsigned t = s_ticket;
        if (t >= T_TOT) break;

        // ---- ticket -> tile ----
        int phase, mat = 0, panel, col0;
        if (t < T_MAIN) {
            const int p = t >> 5, w = t & 31;
            if (w < 24) {
                phase = 1; mat = w >> 3; panel = p; col0 = (w & 7) << 7;
            } else {
                const int p2 = p - LAG;
                if (p2 < 0) continue;            // uniform no-op ticket
                phase = 2; panel = p2; col0 = (w - 24) << 7;
            }
        } else {
            const int u = (int)(t - T_MAIN);
            phase = 2; panel = NPANEL - LAG + (u >> 3); col0 = (u & 7) << 7;
        }
        const int row0 = panel << 7;

        int kstart, KT, astride;
        const __half *Amat, *Bmat;
        if (phase == 1) {
            kstart  = (mat == 2) ? HID : 0;
            KT      = (KCAT - kstart) / BK;      // 32 or 16
            Amat    = g_A;  astride = KCAT;
            Bmat    = g_Wt[mat];
        } else {
            kstart  = 0;
            KT      = HID / BK;                  // 16
            Amat    = g_rh; astride = HID;
            Bmat    = g_Wt[2];
            if (tid == 0) {                      // wait for 24 producers
                volatile unsigned* f = &g_flag[panel];
                while (*f < 24u) { }
            }
            __syncthreads();
            __threadfence();                     // acquire
        }

        auto load_stage = [&](int kt) {
            const uint32_t so = sbase + (kt % NST) * STAGE_B;
            const int kbase = kstart + kt * BK;
            #pragma unroll
            for (int j = 0; j < 4; j++) {        // A: 128 rows x 8 16B-chunks
                int idx = tid + j * 256;
                int r = idx >> 3, c = idx & 7;
                cp16u(so + r * (RS * 2) + c * 16,
                      Amat + (size_t)(row0 + r) * astride + kbase + c * 8);
            }
            #pragma unroll
            for (int j = 0; j < 4; j++) {        // B: 128 n-rows x 8 chunks
                int idx = tid + j * 256;
                int r = idx >> 3, c = idx & 7;
                cp16u(so + A_STAGE_B + r * (RS * 2) + c * 16,
                      Bmat + (size_t)(col0 + r) * KCAT + kbase + c * 8);
            }
            cp_commit();
        };

        float acc[4][4][4];
        #pragma unroll
        for (int mt = 0; mt < 4; mt++)
            #pragma unroll
            for (int nt = 0; nt < 4; nt++)
                #pragma unroll
                for (int i = 0; i < 4; i++)
                    acc[mt][nt][i] = 0.0f;

        load_stage(0);
        load_stage(1);

        for (int kt = 0; kt < KT; kt++) {
            if (kt < KT - 1) cp_wait<1>(); else cp_wait<0>();
            __syncthreads();                 // single barrier per iteration
            if (kt + 2 < KT) load_stage(kt + 2);

            const uint32_t so = sbase + (kt % NST) * STAGE_B;
            #pragma unroll
            for (int ks = 0; ks < 4; ks++) {     // four k16 steps per stage
                uint32_t a[4][4], b[2][4];
                #pragma unroll
                for (int mt = 0; mt < 4; mt++)
                    ldsm4(a[mt], so + a_off[mt] + ks * 32);
                #pragma unroll
                for (int nt2 = 0; nt2 < 2; nt2++)
                    ldsm4(b[nt2], so + b_off[nt2] + ks * 32);
                #pragma unroll
                for (int mt = 0; mt < 4; mt++)
                    #pragma unroll
                    for (int nt = 0; nt < 4; nt++)
                        mma_f16(acc[mt][nt], a[mt], &b[nt >> 1][(nt & 1) * 2]);
            }
            // no trailing barrier: 3-deep ring; next write to this slot is
            // gated by the next top-of-loop barrier.
        }

        // ---- epilogue (variant chosen once per tile) ----
        #pragma unroll
        for (int mt = 0; mt < 4; mt++) {
            #pragma unroll
            for (int nt = 0; nt < 4; nt++) {
                int r = row0 + warp_m * 64 + mt * 16 + (lane >> 2);
                int c = col0 + warp_n * 32 + nt * 8 + (lane & 3) * 2;
                #pragma unroll
                for (int half_i = 0; half_i < 2; half_i++) {
                    int rr = r + half_i * 8;
                    size_t gi = (size_t)rr * HID + c;
                    float v0 = acc[mt][nt][half_i * 2 + 0];
                    float v1 = acc[mt][nt][half_i * 2 + 1];
                    if (phase == 1) {
                        if (mat == 0) {
                            float2 hv = *(const float2*)(h + gi);
                            *(__half2*)(g_rh + gi) = __float22half2_rn(make_float2(
                                sigmoidf_fast(v0) * hv.x, sigmoidf_fast(v1) * hv.y));
                        } else if (mat == 1) {
                            *(__half2*)(g_z + gi) = __float22half2_rn(make_float2(
                                sigmoidf_fast(v0), sigmoidf_fast(v1)));
                        } else {
                            *(__half2*)(g_hp + gi) = __float22half2_rn(make_float2(v0, v1));
                        }
                    } else {
                        float2 hp2 = __half22float2(*(const __half2*)(g_hp + gi));
                        float2 z2  = __half22float2(*(const __half2*)(g_z  + gi));
                        float2 hv2 = *(const float2*)(h + gi);
                        float t0 = tanhf_fast(v0 + hp2.x);
                        float t1 = tanhf_fast(v1 + hp2.y);
                        float2 o;
                        o.x = hv2.x + z2.x * (t0 - hv2.x);
                        o.y = hv2.y + z2.y * (t1 - hv2.y);
                        *(float2*)(out + gi) = o;
                    }
                }
            }
        }

        if (phase == 1) {                    // release: publish this tile
            __threadfence();
            __syncthreads();
            if (tid == 0) atomicAdd(&g_flag[panel], 1u);
        }
    }
}

// ---------------------------------------------------------------------------

extern "C" void kernel_launch(void* const* d_in, const int* in_sizes, int n_in,
                              void* d_out, int out_size)
{
    const float* h  = (const float*)d_in[0];
    const float* x  = (const float*)d_in[1];
    const float* Wr = (const float*)d_in[2];
    const float* Wz = (const float*)d_in[3];
    const float* Wh = (const float*)d_in[4];
    float* out = (float*)d_out;

    cudaFuncSetAttribute(gru_fused, cudaFuncAttributeMaxDynamicSharedMemorySize, SMEM_TOTAL);

    init_kernel<<<1, 128>>>();
    prep_concat_kernel <<<2048, 256>>>(h, x);
    dim3 gT(HID / 32, KCAT / 32, 3);
    prep_weights_kernel<<<gT, dim3(32, 8)>>>(Wr, Wz, Wh);

    gru_fused<<<NCTA, 256, SMEM_TOTAL>>>(h, out);
}

// round 14
// speedup vs baseline: 1.0366x; 1.0366x over previous
#include <cuda_runtime.h>
#include <cuda_fp16.h>
#include <cstdint>
#include <math.h>

// ---------------------------------------------------------------------------
// GRU cell, legacy mma path (tcgen05 rejected by harness PTX target sm_103).
// R14: R13 persistent ticket-scheduled kernel with LAG 12 -> 24.
// R13 post-mortem: consumers of panel p-12 arrived only ~1.3 in-flight ticket
// windows behind their producers -> near-miss spin waits cost ~25% of wall.
// LAG=24 = 2.6 windows: producers finished with margin. Spin adds nanosleep
// backoff. Everything else identical to R13 (tensor packing hit 45.7%, DRAM
// 4.9% -> fusion direction is right, only the dependency distance was wrong).
// ---------------------------------------------------------------------------

#define BATCH   16384
#define HID     1024
#define KCAT    2048
#define BK      64            // k halves per stage (4 x k16 MMA steps)
#define NST     3

#define BM 128
#define BN 128
#define RS 72                               // smem row stride in halves (144 B)
#define A_STAGE_B (BM * RS * 2)             // 18432 B
#define B_STAGE_B (BN * RS * 2)             // 18432 B
#define STAGE_B   (A_STAGE_B + B_STAGE_B)   // 36864 B
#define SMEM_TOTAL (NST * STAGE_B)          // 110592 B (x2 CTAs <= 228 KB)

#define NPANEL 128            // row panels of 128
#define LAG    24             // phase-2 panel lag (>= 2.6 in-flight windows)
#define T_MAIN (NPANEL * 32)                 // 4096 (24 p1 + 8 p2-slots / panel)
#define T_TOT  (T_MAIN + 8 * LAG)            // tail phase-2 for last LAG panels
#define NCTA   296            // 148 SMs x 2 CTAs

// -------------------------- device scratch ---------------------------------
__device__ __half g_A [BATCH * KCAT];
__device__ __half g_Wt[3][HID * KCAT];   // [n][k]
__device__ __half g_rh[BATCH * HID];
__device__ __half g_z [BATCH * HID];
__device__ __half g_hp[BATCH * HID];
__device__ unsigned g_ticket;
__device__ unsigned g_flag[NPANEL];

// -------------------------- helpers ----------------------------------------
__device__ __forceinline__ void mma_f16(float* c, const uint32_t* a, const uint32_t* b) {
    asm volatile(
        "mma.sync.aligned.m16n8k16.row.col.f32.f16.f16.f32 "
        "{%0,%1,%2,%3}, {%4,%5,%6,%7}, {%8,%9}, {%0,%1,%2,%3};\n"
        : "+f"(c[0]), "+f"(c[1]), "+f"(c[2]), "+f"(c[3])
        : "r"(a[0]), "r"(a[1]), "r"(a[2]), "r"(a[3]),
          "r"(b[0]), "r"(b[1]));
}
__device__ __forceinline__ void ldsm4(uint32_t* r, uint32_t addr) {
    asm volatile("ldmatrix.sync.aligned.m8n8.x4.shared.b16 {%0,%1,%2,%3}, [%4];"
                 : "=r"(r[0]), "=r"(r[1]), "=r"(r[2]), "=r"(r[3]) : "r"(addr));
}
__device__ __forceinline__ void cp16u(uint32_t smem_dst, const void* gmem_src) {
    asm volatile("cp.async.cg.shared.global [%0], [%1], 16;" :: "r"(smem_dst), "l"(gmem_src));
}
__device__ __forceinline__ void cp_commit() { asm volatile("cp.async.commit_group;"); }
template <int N>
__device__ __forceinline__ void cp_wait() { asm volatile("cp.async.wait_group %0;" :: "n"(N) : "memory"); }
__device__ __forceinline__ float sigmoidf_fast(float v) { return 1.0f / (1.0f + __expf(-v)); }
__device__ __forceinline__ float tanhf_fast(float v) {
    return 1.0f - 2.0f / (__expf(2.0f * v) + 1.0f);
}

// ---------------------------------------------------------------------------
// Init + prep kernels
// ---------------------------------------------------------------------------
__global__ void init_kernel() {
    if (threadIdx.x == 0) g_ticket = 0;
    if (threadIdx.x < NPANEL) g_flag[threadIdx.x] = 0;
}

__global__ void prep_concat_kernel(const float* __restrict__ h,
                                   const float* __restrict__ x)
{
    size_t n8 = (size_t)BATCH * KCAT / 8;
    for (size_t i = (size_t)blockIdx.x * blockDim.x + threadIdx.x;
         i < n8; i += (size_t)gridDim.x * blockDim.x) {
        size_t e   = i * 8;
        size_t row = e >> 11;
        size_t col = e & (KCAT - 1);
        const float* src = (col < HID) ? (h + row * HID + col)
                                       : (x + row * HID + (col - HID));
        float4 v0 = ((const float4*)src)[0];
        float4 v1 = ((const float4*)src)[1];
        __half2 o[4];
        o[0] = __float22half2_rn(make_float2(v0.x, v0.y));
        o[1] = __float22half2_rn(make_float2(v0.z, v0.w));
        o[2] = __float22half2_rn(make_float2(v1.x, v1.y));
        o[3] = __float22half2_rn(make_float2(v1.z, v1.w));
        ((uint4*)g_A)[i] = *(uint4*)o;
    }
}

__global__ void prep_weights_kernel(const float* __restrict__ Wr,
                                    const float* __restrict__ Wz,
                                    const float* __restrict__ Wh)
{
    __shared__ float t[32][33];
    const float* src = (blockIdx.z == 0) ? Wr : (blockIdx.z == 1) ? Wz : Wh;
    __half* dst = g_Wt[blockIdx.z];
    int tx = threadIdx.x, ty = threadIdx.y;
    int c0 = blockIdx.x * 32;   // n
    int r0 = blockIdx.y * 32;   // k
    #pragma unroll
    for (int j = 0; j < 32; j += 8)
        t[ty + j][tx] = src[(size_t)(r0 + ty + j) * HID + c0 + tx];
    __syncthreads();
    #pragma unroll
    for (int j = 0; j < 32; j += 8)
        dst[(size_t)(c0 + ty + j) * KCAT + r0 + tx] = __float2half_rn(t[tx][ty + j]);
}

// ---------------------------------------------------------------------------
// Persistent fused GEMM kernel.
// ---------------------------------------------------------------------------
__global__ void __launch_bounds__(256, 2)
gru_fused(const float* __restrict__ h, float* __restrict__ out)
{
    extern __shared__ char smem[];
    __shared__ unsigned s_ticket;
    const uint32_t sbase = (uint32_t)__cvta_generic_to_shared(smem);
    const int tid    = threadIdx.x;
    const int lane   = tid & 31;
    const int wid    = tid >> 5;
    const int warp_m = wid >> 2;         // 0..1 -> 64-row band
    const int warp_n = wid & 3;          // 0..3 -> 32-col band

    // per-thread ldmatrix base offsets (bytes within stage) — tile-invariant
    uint32_t a_off[4];
    #pragma unroll
    for (int mt = 0; mt < 4; mt++)
        a_off[mt] = (warp_m * 64 + mt * 16 + (lane & 15)) * (RS * 2)
                  + ((lane >> 4) & 1) * 16;
    uint32_t b_off[2];
    #pragma unroll
    for (int nt2 = 0; nt2 < 2; nt2++)
        b_off[nt2] = A_STAGE_B
                   + (warp_n * 32 + nt2 * 16 + (lane & 7) + ((lane >> 4) & 1) * 8) * (RS * 2)
                   + ((lane >> 3) & 1) * 16;

    for (;;) {
        if (tid == 0) s_ticket = atomicAdd(&g_ticket, 1u);
        __syncthreads();
        const unsigned t = s_ticket;
        if (t >= T_TOT) break;

        // ---- ticket -> tile ----
        int phase, mat = 0, panel, col0;
        if (t < T_MAIN) {
            const int p = t >> 5, w = t & 31;
            if (w < 24) {
                phase = 1; mat = w >> 3; panel = p; col0 = (w & 7) << 7;
            } else {
                const int p2 = p - LAG;
                if (p2 < 0) continue;            // uniform no-op ticket
                phase = 2; panel = p2; col0 = (w - 24) << 7;
            }
        } else {
            const int u = (int)(t - T_MAIN);
            phase = 2; panel = NPANEL - LAG + (u >> 3); col0 = (u & 7) << 7;
        }
        const int row0 = panel << 7;

        int kstart, KT, astride;
        const __half *Amat, *Bmat;
        if (phase == 1) {
            kstart  = (mat == 2) ? HID : 0;
            KT      = (KCAT - kstart) / BK;      // 32 or 16
            Amat    = g_A;  astride = KCAT;
            Bmat    = g_Wt[mat];
        } else {
            kstart  = 0;
            KT      = HID / BK;                  // 16
            Amat    = g_rh; astride = HID;
            Bmat    = g_Wt[2];
            if (tid == 0) {                      // wait for 24 producers
                volatile unsigned* f = &g_flag[panel];
                while (*f < 24u) __nanosleep(64);
            }
            __syncthreads();
            __threadfence();                     // acquire
        }

        auto load_stage = [&](int kt) {
            const uint32_t so = sbase + (kt % NST) * STAGE_B;
            const int kbase = kstart + kt * BK;
            #pragma unroll
            for (int j = 0; j < 4; j++) {        // A: 128 rows x 8 16B-chunks
                int idx = tid + j * 256;
                int r = idx >> 3, c = idx & 7;
                cp16u(so + r * (RS * 2) + c * 16,
                      Amat + (size_t)(row0 + r) * astride + kbase + c * 8);
            }
            #pragma unroll
            for (int j = 0; j < 4; j++) {        // B: 128 n-rows x 8 chunks
                int idx = tid + j * 256;
                int r = idx >> 3, c = idx & 7;
                cp16u(so + A_STAGE_B + r * (RS * 2) + c * 16,
                      Bmat + (size_t)(col0 + r) * KCAT + kbase + c * 8);
            }
            cp_commit();
        };

        float acc[4][4][4];
        #pragma unroll
        for (int mt = 0; mt < 4; mt++)
            #pragma unroll
            for (int nt = 0; nt < 4; nt++)
                #pragma unroll
                for (int i = 0; i < 4; i++)
                    acc[mt][nt][i] = 0.0f;

        load_stage(0);
        load_stage(1);

        for (int kt = 0; kt < KT; kt++) {
            if (kt < KT - 1) cp_wait<1>(); else cp_wait<0>();
            __syncthreads();                 // single barrier per iteration
            if (kt + 2 < KT) load_stage(kt + 2);

            const uint32_t so = sbase + (kt % NST) * STAGE_B;
            #pragma unroll
            for (int ks = 0; ks < 4; ks++) {     // four k16 steps per stage
                uint32_t a[4][4], b[2][4];
                #pragma unroll
                for (int mt = 0; mt < 4; mt++)
                    ldsm4(a[mt], so + a_off[mt] + ks * 32);
                #pragma unroll
                for (int nt2 = 0; nt2 < 2; nt2++)
                    ldsm4(b[nt2], so + b_off[nt2] + ks * 32);
                #pragma unroll
                for (int mt = 0; mt < 4; mt++)
                    #pragma unroll
                    for (int nt = 0; nt < 4; nt++)
                        mma_f16(acc[mt][nt], a[mt], &b[nt >> 1][(nt & 1) * 2]);
            }
            // no trailing barrier: 3-deep ring; next write to this slot is
            // gated by the next top-of-loop barrier.
        }

        // ---- epilogue (variant chosen once per tile) ----
        #pragma unroll
        for (int mt = 0; mt < 4; mt++) {
            #pragma unroll
            for (int nt = 0; nt < 4; nt++) {
                int r = row0 + warp_m * 64 + mt * 16 + (lane >> 2);
                int c = col0 + warp_n * 32 + nt * 8 + (lane & 3) * 2;
                #pragma unroll
                for (int half_i = 0; half_i < 2; half_i++) {
                    int rr = r + half_i * 8;
                    size_t gi = (size_t)rr * HID + c;
                    float v0 = acc[mt][nt][half_i * 2 + 0];
                    float v1 = acc[mt][nt][half_i * 2 + 1];
                    if (phase == 1) {
                        if (mat == 0) {
                            float2 hv = *(const float2*)(h + gi);
                            *(__half2*)(g_rh + gi) = __float22half2_rn(make_float2(
                                sigmoidf_fast(v0) * hv.x, sigmoidf_fast(v1) * hv.y));
                        } else if (mat == 1) {
                            *(__half2*)(g_z + gi) = __float22half2_rn(make_float2(
                                sigmoidf_fast(v0), sigmoidf_fast(v1)));
                        } else {
                            *(__half2*)(g_hp + gi) = __float22half2_rn(make_float2(v0, v1));
                        }
                    } else {
                        float2 hp2 = __half22float2(*(const __half2*)(g_hp + gi));
                        float2 z2  = __half22float2(*(const __half2*)(g_z  + gi));
                        float2 hv2 = *(const float2*)(h + gi);
                        float t0 = tanhf_fast(v0 + hp2.x);
                        float t1 = tanhf_fast(v1 + hp2.y);
                        float2 o;
                        o.x = hv2.x + z2.x * (t0 - hv2.x);
                        o.y = hv2.y + z2.y * (t1 - hv2.y);
                        *(float2*)(out + gi) = o;
                    }
                }
            }
        }

        if (phase == 1) {                    // release: publish this tile
            __threadfence();
            __syncthreads();
            if (tid == 0) atomicAdd(&g_flag[panel], 1u);
        }
    }
}

// ---------------------------------------------------------------------------

extern "C" void kernel_launch(void* const* d_in, const int* in_sizes, int n_in,
                              void* d_out, int out_size)
{
    const float* h  = (const float*)d_in[0];
    const float* x  = (const float*)d_in[1];
    const float* Wr = (const float*)d_in[2];
    const float* Wz = (const float*)d_in[3];
    const float* Wh = (const float*)d_in[4];
    float* out = (float*)d_out;

    cudaFuncSetAttribute(gru_fused, cudaFuncAttributeMaxDynamicSharedMemorySize, SMEM_TOTAL);

    init_kernel<<<1, 128>>>();
    prep_concat_kernel <<<2048, 256>>>(h, x);
    dim3 gT(HID / 32, KCAT / 32, 3);
    prep_weights_kernel<<<gT, dim3(32, 8)>>>(Wr, Wz, Wh);

    gru_fused<<<NCTA, 256, SMEM_TOTAL>>>(h, out);
}

// round 15
// speedup vs baseline: 1.1316x; 1.0917x over previous
#include <cuda_runtime.h>
#include <cuda_fp16.h>
#include <cstdint>
#include <math.h>

// ---------------------------------------------------------------------------
// GRU cell, legacy mma path (tcgen05 rejected by harness PTX target sm_103).
// R15: dependency-aware two-kernel split.
//   Kernel A: r-gate GEMM (K=2048) -> g_rh            (critical path only)
//   Kernel B: per CTA, ONE virtual K=64-iter pipeline chaining
//       kt  0..31 : z  = g_A x Wt_z            (acc -> sigmoid -> g_z, zero)
//       kt 32..47 : hp = g_A[x] x Wt_h[1024:]  (accumulate)
//       kt 48..63 : +    g_rh x Wt_h[:1024]    (same accumulator!)
//     epilogue: out = h + z*(tanh(acc) - h).   hp scratch eliminated.
// One prologue/epilogue per 64 k-iters (R12 paid 3 pipeline fills; measured
// packing 57% @KT=32 vs 40% @KT=16 is the amortization effect being bought).
// Mainloop config = exact R12: 128x128 tile, 8 warps 64x32, BK=64, NST=3,
// single barrier/iter, fp16 ldmatrix+mma, 2 CTA/SM.
// ---------------------------------------------------------------------------

#define BATCH   16384
#define HID     1024
#define KCAT    2048
#define BK      64            // k halves per stage (4 x k16 MMA steps)
#define NST     3

#define BM 128
#define BN 128
#define RS 72                               // smem row stride in halves (144 B)
#define A_STAGE_B (BM * RS * 2)             // 18432 B
#define B_STAGE_B (BN * RS * 2)             // 18432 B
#define STAGE_B   (A_STAGE_B + B_STAGE_B)   // 36864 B
#define SMEM_TOTAL (NST * STAGE_B)          // 110592 B (x2 CTAs <= 228 KB)

// Kernel B virtual K schedule
#define KT_TOT 64
#define KB_HP  32             // hp segment start
#define KB_P2  48             // g_rh segment start

// -------------------------- device scratch ---------------------------------
__device__ __half g_A [BATCH * KCAT];
__device__ __half g_Wt[3][HID * KCAT];   // [n][k]
__device__ __half g_rh[BATCH * HID];
__device__ __half g_z [BATCH * HID];

// -------------------------- helpers ----------------------------------------
__device__ __forceinline__ void mma_f16(float* c, const uint32_t* a, const uint32_t* b) {
    asm volatile(
        "mma.sync.aligned.m16n8k16.row.col.f32.f16.f16.f32 "
        "{%0,%1,%2,%3}, {%4,%5,%6,%7}, {%8,%9}, {%0,%1,%2,%3};\n"
        : "+f"(c[0]), "+f"(c[1]), "+f"(c[2]), "+f"(c[3])
        : "r"(a[0]), "r"(a[1]), "r"(a[2]), "r"(a[3]),
          "r"(b[0]), "r"(b[1]));
}
__device__ __forceinline__ void ldsm4(uint32_t* r, uint32_t addr) {
    asm volatile("ldmatrix.sync.aligned.m8n8.x4.shared.b16 {%0,%1,%2,%3}, [%4];"
                 : "=r"(r[0]), "=r"(r[1]), "=r"(r[2]), "=r"(r[3]) : "r"(addr));
}
__device__ __forceinline__ void cp16u(uint32_t smem_dst, const void* gmem_src) {
    asm volatile("cp.async.cg.shared.global [%0], [%1], 16;" :: "r"(smem_dst), "l"(gmem_src));
}
__device__ __forceinline__ void cp_commit() { asm volatile("cp.async.commit_group;"); }
template <int N>
__device__ __forceinline__ void cp_wait() { asm volatile("cp.async.wait_group %0;" :: "n"(N) : "memory"); }
__device__ __forceinline__ float sigmoidf_fast(float v) { return 1.0f / (1.0f + __expf(-v)); }
__device__ __forceinline__ float tanhf_fast(float v) {
    return 1.0f - 2.0f / (__expf(2.0f * v) + 1.0f);
}

// ---------------------------------------------------------------------------
// Prep kernels
// ---------------------------------------------------------------------------
__global__ void prep_concat_kernel(const float* __restrict__ h,
                                   const float* __restrict__ x)
{
    size_t n8 = (size_t)BATCH * KCAT / 8;
    for (size_t i = (size_t)blockIdx.x * blockDim.x + threadIdx.x;
         i < n8; i += (size_t)gridDim.x * blockDim.x) {
        size_t e   = i * 8;
        size_t row = e >> 11;
        size_t col = e & (KCAT - 1);
        const float* src = (col < HID) ? (h + row * HID + col)
                                       : (x + row * HID + (col - HID));
        float4 v0 = ((const float4*)src)[0];
        float4 v1 = ((const float4*)src)[1];
        __half2 o[4];
        o[0] = __float22half2_rn(make_float2(v0.x, v0.y));
        o[1] = __float22half2_rn(make_float2(v0.z, v0.w));
        o[2] = __float22half2_rn(make_float2(v1.x, v1.y));
        o[3] = __float22half2_rn(make_float2(v1.z, v1.w));
        ((uint4*)g_A)[i] = *(uint4*)o;
    }
}

// transpose + convert: g_Wt[g][n][k] = half(W_g[k][n])
__global__ void prep_weights_kernel(const float* __restrict__ Wr,
                                    const float* __restrict__ Wz,
                                    const float* __restrict__ Wh)
{
    __shared__ float t[32][33];
    const float* src = (blockIdx.z == 0) ? Wr : (blockIdx.z == 1) ? Wz : Wh;
    __half* dst = g_Wt[blockIdx.z];
    int tx = threadIdx.x, ty = threadIdx.y;
    int c0 = blockIdx.x * 32;   // n
    int r0 = blockIdx.y * 32;   // k
    #pragma unroll
    for (int j = 0; j < 32; j += 8)
        t[ty + j][tx] = src[(size_t)(r0 + ty + j) * HID + c0 + tx];
    __syncthreads();
    #pragma unroll
    for (int j = 0; j < 32; j += 8)
        dst[(size_t)(c0 + ty + j) * KCAT + r0 + tx] = __float2half_rn(t[tx][ty + j]);
}

// ---------------------------------------------------------------------------
// Kernel A: r-gate GEMM (exact R12 MODE1/mat0).
// ---------------------------------------------------------------------------
__global__ void __launch_bounds__(256, 2)
gru_rgate(const float* __restrict__ h)
{
    extern __shared__ char smem[];
    const uint32_t sbase = (uint32_t)__cvta_generic_to_shared(smem);
    const int tid    = threadIdx.x;
    const int lane   = tid & 31;
    const int wid    = tid >> 5;
    const int warp_m = wid >> 2;
    const int warp_n = wid & 3;
    const int col0   = blockIdx.x * BN;
    const int row0   = blockIdx.y * BM;
    const int KT     = KCAT / BK;        // 32

    auto load_stage = [&](int kt) {
        const uint32_t so = sbase + (kt % NST) * STAGE_B;
        const int kbase = kt * BK;
        #pragma unroll
        for (int j = 0; j < 4; j++) {
            int idx = tid + j * 256;
            int r = idx >> 3, c = idx & 7;
            cp16u(so + r * (RS * 2) + c * 16,
                  g_A + (size_t)(row0 + r) * KCAT + kbase + c * 8);
        }
        #pragma unroll
        for (int j = 0; j < 4; j++) {
            int idx = tid + j * 256;
            int r = idx >> 3, c = idx & 7;
            cp16u(so + A_STAGE_B + r * (RS * 2) + c * 16,
                  g_Wt[0] + (size_t)(col0 + r) * KCAT + kbase + c * 8);
        }
        cp_commit();
    };

    uint32_t a_off[4];
    #pragma unroll
    for (int mt = 0; mt < 4; mt++)
        a_off[mt] = (warp_m * 64 + mt * 16 + (lane & 15)) * (RS * 2)
                  + ((lane >> 4) & 1) * 16;
    uint32_t b_off[2];
    #pragma unroll
    for (int nt2 = 0; nt2 < 2; nt2++)
        b_off[nt2] = A_STAGE_B
                   + (warp_n * 32 + nt2 * 16 + (lane & 7) + ((lane >> 4) & 1) * 8) * (RS * 2)
                   + ((lane >> 3) & 1) * 16;

    float acc[4][4][4];
    #pragma unroll
    for (int mt = 0; mt < 4; mt++)
        #pragma unroll
        for (int nt = 0; nt < 4; nt++)
            #pragma unroll
            for (int i = 0; i < 4; i++)
                acc[mt][nt][i] = 0.0f;

    load_stage(0);
    load_stage(1);

    for (int kt = 0; kt < KT; kt++) {
        if (kt < KT - 1) cp_wait<1>(); else cp_wait<0>();
        __syncthreads();
        if (kt + 2 < KT) load_stage(kt + 2);

        const uint32_t so = sbase + (kt % NST) * STAGE_B;
        #pragma unroll
        for (int ks = 0; ks < 4; ks++) {
            uint32_t a[4][4], b[2][4];
            #pragma unroll
            for (int mt = 0; mt < 4; mt++)
                ldsm4(a[mt], so + a_off[mt] + ks * 32);
            #pragma unroll
            for (int nt2 = 0; nt2 < 2; nt2++)
                ldsm4(b[nt2], so + b_off[nt2] + ks * 32);
            #pragma unroll
            for (int mt = 0; mt < 4; mt++)
                #pragma unroll
                for (int nt = 0; nt < 4; nt++)
                    mma_f16(acc[mt][nt], a[mt], &b[nt >> 1][(nt & 1) * 2]);
        }
    }

    #pragma unroll
    for (int mt = 0; mt < 4; mt++) {
        #pragma unroll
        for (int nt = 0; nt < 4; nt++) {
            int r = row0 + warp_m * 64 + mt * 16 + (lane >> 2);
            int c = col0 + warp_n * 32 + nt * 8 + (lane & 3) * 2;
            #pragma unroll
            for (int half_i = 0; half_i < 2; half_i++) {
                int rr = r + half_i * 8;
                size_t gi = (size_t)rr * HID + c;
                float v0 = acc[mt][nt][half_i * 2 + 0];
                float v1 = acc[mt][nt][half_i * 2 + 1];
                float2 hv = *(const float2*)(h + gi);
                *(__half2*)(g_rh + gi) = __float22half2_rn(make_float2(
                    sigmoidf_fast(v0) * hv.x, sigmoidf_fast(v1) * hv.y));
            }
        }
    }
}

// ---------------------------------------------------------------------------
// Kernel B: chained z / hp / p2 GEMM (virtual KT=64), blend epilogue.
// ---------------------------------------------------------------------------
__global__ void __launch_bounds__(256, 2)
gru_zht(const float* __restrict__ h, float* __restrict__ out)
{
    extern __shared__ char smem[];
    const uint32_t sbase = (uint32_t)__cvta_generic_to_shared(smem);
    const int tid    = threadIdx.x;
    const int lane   = tid & 31;
    const int wid    = tid >> 5;
    const int warp_m = wid >> 2;
    const int warp_n = wid & 3;
    const int col0   = blockIdx.x * BN;
    const int row0   = blockIdx.y * BM;

    // virtual-kt -> (A source, strides, k offsets). Uniform per iteration.
    auto load_stage = [&](int kt) {
        const uint32_t so = sbase + (kt % NST) * STAGE_B;
        const __half* Amat;
        int astride, kbase, bbase;
        const __half* Bmat;
        if (kt < KB_HP)      { Amat = g_A;  astride = KCAT; kbase = kt * BK;
                               Bmat = g_Wt[1]; bbase = kbase; }
        else if (kt < KB_P2) { Amat = g_A;  astride = KCAT; kbase = (kt - 16) * BK;  // 1024 + (kt-32)*64
                               Bmat = g_Wt[2]; bbase = kbase; }
        else                 { Amat = g_rh; astride = HID;  kbase = (kt - KB_P2) * BK;
                               Bmat = g_Wt[2]; bbase = kbase; }
        #pragma unroll
        for (int j = 0; j < 4; j++) {
            int idx = tid + j * 256;
            int r = idx >> 3, c = idx & 7;
            cp16u(so + r * (RS * 2) + c * 16,
                  Amat + (size_t)(row0 + r) * astride + kbase + c * 8);
        }
        #pragma unroll
        for (int j = 0; j < 4; j++) {
            int idx = tid + j * 256;
            int r = idx >> 3, c = idx & 7;
            cp16u(so + A_STAGE_B + r * (RS * 2) + c * 16,
                  Bmat + (size_t)(col0 + r) * KCAT + bbase + c * 8);
        }
        cp_commit();
    };

    uint32_t a_off[4];
    #pragma unroll
    for (int mt = 0; mt < 4; mt++)
        a_off[mt] = (warp_m * 64 + mt * 16 + (lane & 15)) * (RS * 2)
                  + ((lane >> 4) & 1) * 16;
    uint32_t b_off[2];
    #pragma unroll
    for (int nt2 = 0; nt2 < 2; nt2++)
        b_off[nt2] = A_STAGE_B
                   + (warp_n * 32 + nt2 * 16 + (lane & 7) + ((lane >> 4) & 1) * 8) * (RS * 2)
                   + ((lane >> 3) & 1) * 16;

    float acc[4][4][4];
    #pragma unroll
    for (int mt = 0; mt < 4; mt++)
        #pragma unroll
        for (int nt = 0; nt < 4; nt++)
            #pragma unroll
            for (int i = 0; i < 4; i++)
                acc[mt][nt][i] = 0.0f;

    load_stage(0);
    load_stage(1);

    for (int kt = 0; kt < KT_TOT; kt++) {
        if (kt < KT_TOT - 1) cp_wait<1>(); else cp_wait<0>();
        __syncthreads();
        if (kt + 2 < KT_TOT) load_stage(kt + 2);

        if (kt == KB_HP) {
            // z handoff: stash sigmoid(acc) to g_z (same thread reloads it
            // in the final epilogue -> same-address, same-thread, L1-hot),
            // then reset the accumulator for the hp+p2 segments.
            #pragma unroll
            for (int mt = 0; mt < 4; mt++) {
                #pragma unroll
                for (int nt = 0; nt < 4; nt++) {
                    int r = row0 + warp_m * 64 + mt * 16 + (lane >> 2);
                    int c = col0 + warp_n * 32 + nt * 8 + (lane & 3) * 2;
                    #pragma unroll
                    for (int half_i = 0; half_i < 2; half_i++) {
                        size_t gi = (size_t)(r + half_i * 8) * HID + c;
                        *(__half2*)(g_z + gi) = __float22half2_rn(make_float2(
                            sigmoidf_fast(acc[mt][nt][half_i * 2 + 0]),
                            sigmoidf_fast(acc[mt][nt][half_i * 2 + 1])));
                        acc[mt][nt][half_i * 2 + 0] = 0.0f;
                        acc[mt][nt][half_i * 2 + 1] = 0.0f;
                    }
                }
            }
        }

        const uint32_t so = sbase + (kt % NST) * STAGE_B;
        #pragma unroll
        for (int ks = 0; ks < 4; ks++) {
            uint32_t a[4][4], b[2][4];
            #pragma unroll
            for (int mt = 0; mt < 4; mt++)
                ldsm4(a[mt], so + a_off[mt] + ks * 32);
            #pragma unroll
            for (int nt2 = 0; nt2 < 2; nt2++)
                ldsm4(b[nt2], so + b_off[nt2] + ks * 32);
            #pragma unroll
            for (int mt = 0; mt < 4; mt++)
                #pragma unroll
                for (int nt = 0; nt < 4; nt++)
                    mma_f16(acc[mt][nt], a[mt], &b[nt >> 1][(nt & 1) * 2]);
        }
    }

    // ---- blend epilogue: out = h + z*(tanh(acc) - h) ----
    #pragma unroll
    for (int mt = 0; mt < 4; mt++) {
        #pragma unroll
        for (int nt = 0; nt < 4; nt++) {
            int r = row0 + warp_m * 64 + mt * 16 + (lane >> 2);
            int c = col0 + warp_n * 32 + nt * 8 + (lane & 3) * 2;
            #pragma unroll
            for (int half_i = 0; half_i < 2; half_i++) {
                size_t gi = (size_t)(r + half_i * 8) * HID + c;
                float v0 = acc[mt][nt][half_i * 2 + 0];
                float v1 = acc[mt][nt][half_i * 2 + 1];
                float2 z2  = __half22float2(*(const __half2*)(g_z + gi));
                float2 hv2 = *(const float2*)(h + gi);
                float t0 = tanhf_fast(v0);
                float t1 = tanhf_fast(v1);
                float2 o;
                o.x = hv2.x + z2.x * (t0 - hv2.x);
                o.y = hv2.y + z2.y * (t1 - hv2.y);
                *(float2*)(out + gi) = o;
            }
        }
    }
}

// ---------------------------------------------------------------------------

extern "C" void kernel_launch(void* const* d_in, const int* in_sizes, int n_in,
                              void* d_out, int out_size)
{
    const float* h  = (const float*)d_in[0];
    const float* x  = (const float*)d_in[1];
    const float* Wr = (const float*)d_in[2];
    const float* Wz = (const float*)d_in[3];
    const float* Wh = (const float*)d_in[4];
    float* out = (float*)d_out;

    cudaFuncSetAttribute(gru_rgate, cudaFuncAttributeMaxDynamicSharedMemorySize, SMEM_TOTAL);
    cudaFuncSetAttribute(gru_zht,   cudaFuncAttributeMaxDynamicSharedMemorySize, SMEM_TOTAL);

    prep_concat_kernel <<<2048, 256>>>(h, x);
    dim3 gT(HID / 32, KCAT / 32, 3);
    prep_weights_kernel<<<gT, dim3(32, 8)>>>(Wr, Wz, Wh);

    dim3 g(HID / BN, BATCH / BM);    // (8, 128)
    gru_rgate<<<g, 256, SMEM_TOTAL>>>(h);
    gru_zht  <<<g, 256, SMEM_TOTAL>>>(h, out);
}

// round 16
// speedup vs baseline: 1.1562x; 1.0217x over previous
#include <cuda_runtime.h>
#include <cuda_fp16.h>
#include <cstdint>
#include <math.h>

// ---------------------------------------------------------------------------
// GRU cell, legacy mma path (tcgen05 rejected by harness PTX target sm_103).
// R16: ONE GEMM launch, blockIdx-ordered dispatch (fusion without tickets).
//   blocks    0..1023 : r-gate tiles  (K=2048) -> g_rh          [producers]
//   blocks 1024..2047 : chained z/hp/p2 tiles (virtual KT=64)   [consumers]
//       kt  0..31 : z  = g_A x Wt_z   (acc -> sigmoid -> g_z, zero acc)
//       kt 32..47 : hp = g_A[x] x Wt_h[1024:]
//       kt 48..63 : +    g_rh x Wt_h[:1024]  (same accumulator)
//     per-panel flag (8 producers) checked once at kt=46, just before the
//     pipeline prefetches the first g_rh stage. Blocks are scheduled in index
//     order => producers always precede consumers => no deadlock, ~zero spin.
// Mainloop = R12/R15 proven config: 128x128 tile, 8 warps 64x32, BK=64,
// NST=3, single barrier/iter, fp16 ldmatrix+mma, 2 CTA/SM.
// ---------------------------------------------------------------------------

#define BATCH   16384
#define HID     1024
#define KCAT    2048
#define BK      64            // k halves per stage (4 x k16 MMA steps)
#define NST     3

#define BM 128
#define BN 128
#define RS 72                               // smem row stride in halves (144 B)
#define A_STAGE_B (BM * RS * 2)             // 18432 B
#define B_STAGE_B (BN * RS * 2)             // 18432 B
#define STAGE_B   (A_STAGE_B + B_STAGE_B)   // 36864 B
#define SMEM_TOTAL (NST * STAGE_B)          // 110592 B (x2 CTAs <= 228 KB)

// zht virtual K schedule
#define KT_TOT 64
#define KB_HP  32             // hp segment start
#define KB_P2  48             // g_rh segment start

#define NPANEL 128
#define NBLK_R 1024           // r-gate tiles
#define NBLK   2048

// -------------------------- device scratch ---------------------------------
__device__ __half g_A [BATCH * KCAT];
__device__ __half g_Wt[3][HID * KCAT];   // [n][k]
__device__ __half g_rh[BATCH * HID];
__device__ __half g_z [BATCH * HID];
__device__ unsigned g_flag[NPANEL];

// -------------------------- helpers ----------------------------------------
__device__ __forceinline__ void mma_f16(float* c, const uint32_t* a, const uint32_t* b) {
    asm volatile(
        "mma.sync.aligned.m16n8k16.row.col.f32.f16.f16.f32 "
        "{%0,%1,%2,%3}, {%4,%5,%6,%7}, {%8,%9}, {%0,%1,%2,%3};\n"
        : "+f"(c[0]), "+f"(c[1]), "+f"(c[2]), "+f"(c[3])
        : "r"(a[0]), "r"(a[1]), "r"(a[2]), "r"(a[3]),
          "r"(b[0]), "r"(b[1]));
}
__device__ __forceinline__ void ldsm4(uint32_t* r, uint32_t addr) {
    asm volatile("ldmatrix.sync.aligned.m8n8.x4.shared.b16 {%0,%1,%2,%3}, [%4];"
                 : "=r"(r[0]), "=r"(r[1]), "=r"(r[2]), "=r"(r[3]) : "r"(addr));
}
__device__ __forceinline__ void cp16u(uint32_t smem_dst, const void* gmem_src) {
    asm volatile("cp.async.cg.shared.global [%0], [%1], 16;" :: "r"(smem_dst), "l"(gmem_src));
}
__device__ __forceinline__ void cp_commit() { asm volatile("cp.async.commit_group;"); }
template <int N>
__device__ __forceinline__ void cp_wait() { asm volatile("cp.async.wait_group %0;" :: "n"(N) : "memory"); }
__device__ __forceinline__ float sigmoidf_fast(float v) { return 1.0f / (1.0f + __expf(-v)); }
__device__ __forceinline__ float tanhf_fast(float v) {
    return 1.0f - 2.0f / (__expf(2.0f * v) + 1.0f);
}

// ---------------------------------------------------------------------------
// Init + prep kernels
// ---------------------------------------------------------------------------
__global__ void init_kernel() {
    if (threadIdx.x < NPANEL) g_flag[threadIdx.x] = 0;
}

__global__ void prep_concat_kernel(const float* __restrict__ h,
                                   const float* __restrict__ x)
{
    size_t n8 = (size_t)BATCH * KCAT / 8;
    for (size_t i = (size_t)blockIdx.x * blockDim.x + threadIdx.x;
         i < n8; i += (size_t)gridDim.x * blockDim.x) {
        size_t e   = i * 8;
        size_t row = e >> 11;
        size_t col = e & (KCAT - 1);
        const float* src = (col < HID) ? (h + row * HID + col)
                                       : (x + row * HID + (col - HID));
        float4 v0 = ((const float4*)src)[0];
        float4 v1 = ((const float4*)src)[1];
        __half2 o[4];
        o[0] = __float22half2_rn(make_float2(v0.x, v0.y));
        o[1] = __float22half2_rn(make_float2(v0.z, v0.w));
        o[2] = __float22half2_rn(make_float2(v1.x, v1.y));
        o[3] = __float22half2_rn(make_float2(v1.z, v1.w));
        ((uint4*)g_A)[i] = *(uint4*)o;
    }
}

__global__ void prep_weights_kernel(const float* __restrict__ Wr,
                                    const float* __restrict__ Wz,
                                    const float* __restrict__ Wh)
{
    __shared__ float t[32][33];
    const float* src = (blockIdx.z == 0) ? Wr : (blockIdx.z == 1) ? Wz : Wh;
    __half* dst = g_Wt[blockIdx.z];
    int tx = threadIdx.x, ty = threadIdx.y;
    int c0 = blockIdx.x * 32;   // n
    int r0 = blockIdx.y * 32;   // k
    #pragma unroll
    for (int j = 0; j < 32; j += 8)
        t[ty + j][tx] = src[(size_t)(r0 + ty + j) * HID + c0 + tx];
    __syncthreads();
    #pragma unroll
    for (int j = 0; j < 32; j += 8)
        dst[(size_t)(c0 + ty + j) * KCAT + r0 + tx] = __float2half_rn(t[tx][ty + j]);
}

// ---------------------------------------------------------------------------
// Fused GEMM kernel: blockIdx-ordered producer/consumer dispatch.
// ---------------------------------------------------------------------------
__global__ void __launch_bounds__(256, 2)
gru_all(const float* __restrict__ h, float* __restrict__ out)
{
    extern __shared__ char smem[];
    const uint32_t sbase = (uint32_t)__cvta_generic_to_shared(smem);
    const int tid    = threadIdx.x;
    const int lane   = tid & 31;
    const int wid    = tid >> 5;
    const int warp_m = wid >> 2;         // 0..1 -> 64-row band
    const int warp_n = wid & 3;          // 0..3 -> 32-col band
    const int bid    = blockIdx.x;

    const bool is_r  = (bid < NBLK_R);
    const int  lbid  = is_r ? bid : (bid - NBLK_R);
    const int  panel = lbid >> 3;
    const int  col0  = (lbid & 7) << 7;
    const int  row0  = panel << 7;
    const int  KT    = is_r ? (KCAT / BK) : KT_TOT;   // 32 or 64

    // per-thread ldmatrix base offsets (bytes within stage)
    uint32_t a_off[4];
    #pragma unroll
    for (int mt = 0; mt < 4; mt++)
        a_off[mt] = (warp_m * 64 + mt * 16 + (lane & 15)) * (RS * 2)
                  + ((lane >> 4) & 1) * 16;
    uint32_t b_off[2];
    #pragma unroll
    for (int nt2 = 0; nt2 < 2; nt2++)
        b_off[nt2] = A_STAGE_B
                   + (warp_n * 32 + nt2 * 16 + (lane & 7) + ((lane >> 4) & 1) * 8) * (RS * 2)
                   + ((lane >> 3) & 1) * 16;

    // virtual-kt -> operands
    auto load_stage = [&](int kt) {
        const uint32_t so = sbase + (kt % NST) * STAGE_B;
        const __half* Amat;
        const __half* Bmat;
        int astride, kbase;
        if (is_r) {
            Amat = g_A;  astride = KCAT; kbase = kt * BK;  Bmat = g_Wt[0];
        } else if (kt < KB_HP) {
            Amat = g_A;  astride = KCAT; kbase = kt * BK;  Bmat = g_Wt[1];
        } else if (kt < KB_P2) {
            Amat = g_A;  astride = KCAT; kbase = (kt - 16) * BK;  Bmat = g_Wt[2];
        } else {
            Amat = g_rh; astride = HID;  kbase = (kt - KB_P2) * BK;  Bmat = g_Wt[2];
        }
        #pragma unroll
        for (int j = 0; j < 4; j++) {
            int idx = tid + j * 256;
            int r = idx >> 3, c = idx & 7;
            cp16u(so + r * (RS * 2) + c * 16,
                  Amat + (size_t)(row0 + r) * astride + kbase + c * 8);
        }
        #pragma unroll
        for (int j = 0; j < 4; j++) {
            int idx = tid + j * 256;
            int r = idx >> 3, c = idx & 7;
            cp16u(so + A_STAGE_B + r * (RS * 2) + c * 16,
                  Bmat + (size_t)(col0 + r) * KCAT + kbase + c * 8);
        }
        cp_commit();
    };

    float acc[4][4][4];
    #pragma unroll
    for (int mt = 0; mt < 4; mt++)
        #pragma unroll
        for (int nt = 0; nt < 4; nt++)
            #pragma unroll
            for (int i = 0; i < 4; i++)
                acc[mt][nt][i] = 0.0f;

    load_stage(0);
    load_stage(1);

    for (int kt = 0; kt < KT; kt++) {
        if (kt < KT - 1) cp_wait<1>(); else cp_wait<0>();
        __syncthreads();                 // single barrier per iteration
        if (kt + 2 < KT) {
            // consumers: gate the FIRST prefetch that touches g_rh on the
            // per-panel producer flag (8 r-gate tiles). Producers were all
            // scheduled before any consumer started -> near-zero spin.
            if (!is_r && (kt + 2) == KB_P2) {
                if (tid == 0) {
                    volatile unsigned* f = &g_flag[panel];
                    while (*f < 8u) __nanosleep(64);
                }
                __syncthreads();
                __threadfence();         // acquire
            }
            load_stage(kt + 2);
        }

        if (!is_r && kt == KB_HP) {
            // z handoff: stash sigmoid(acc) -> g_z (same thread reloads in
            // the blend epilogue; L1-hot), zero the accumulator.
            #pragma unroll
            for (int mt = 0; mt < 4; mt++) {
                #pragma unroll
                for (int nt = 0; nt < 4; nt++) {
                    int r = row0 + warp_m * 64 + mt * 16 + (lane >> 2);
                    int c = col0 + warp_n * 32 + nt * 8 + (lane & 3) * 2;
                    #pragma unroll
                    for (int half_i = 0; half_i < 2; half_i++) {
                        size_t gi = (size_t)(r + half_i * 8) * HID + c;
                        *(__half2*)(g_z + gi) = __float22half2_rn(make_float2(
                            sigmoidf_fast(acc[mt][nt][half_i * 2 + 0]),
                            sigmoidf_fast(acc[mt][nt][half_i * 2 + 1])));
                        acc[mt][nt][half_i * 2 + 0] = 0.0f;
                        acc[mt][nt][half_i * 2 + 1] = 0.0f;
                    }
                }
            }
        }

        const uint32_t so = sbase + (kt % NST) * STAGE_B;
        #pragma unroll
        for (int ks = 0; ks < 4; ks++) {     // four k16 steps per stage
            uint32_t a[4][4], b[2][4];
            #pragma unroll
            for (int mt = 0; mt < 4; mt++)
                ldsm4(a[mt], so + a_off[mt] + ks * 32);
            #pragma unroll
            for (int nt2 = 0; nt2 < 2; nt2++)
                ldsm4(b[nt2], so + b_off[nt2] + ks * 32);
            #pragma unroll
            for (int mt = 0; mt < 4; mt++)
                #pragma unroll
                for (int nt = 0; nt < 4; nt++)
                    mma_f16(acc[mt][nt], a[mt], &b[nt >> 1][(nt & 1) * 2]);
        }
        // no trailing barrier: 3-deep ring; next write to this slot is gated
        // by the next top-of-loop barrier.
    }

    // ---- epilogue ----
    if (is_r) {
        #pragma unroll
        for (int mt = 0; mt < 4; mt++) {
            #pragma unroll
            for (int nt = 0; nt < 4; nt++) {
                int r = row0 + warp_m * 64 + mt * 16 + (lane >> 2);
                int c = col0 + warp_n * 32 + nt * 8 + (lane & 3) * 2;
                #pragma unroll
                for (int half_i = 0; half_i < 2; half_i++) {
                    size_t gi = (size_t)(r + half_i * 8) * HID + c;
                    float v0 = acc[mt][nt][half_i * 2 + 0];
                    float v1 = acc[mt][nt][half_i * 2 + 1];
                    float2 hv = *(const float2*)(h + gi);
                    *(__half2*)(g_rh + gi) = __float22half2_rn(make_float2(
                        sigmoidf_fast(v0) * hv.x, sigmoidf_fast(v1) * hv.y));
                }
            }
        }
        __threadfence();                 // release g_rh tile
        __syncthreads();
        if (tid == 0) atomicAdd(&g_flag[panel], 1u);
    } else {
        #pragma unroll
        for (int mt = 0; mt < 4; mt++) {
            #pragma unroll
            for (int nt = 0; nt < 4; nt++) {
                int r = row0 + warp_m * 64 + mt * 16 + (lane >> 2);
                int c = col0 + warp_n * 32 + nt * 8 + (lane & 3) * 2;
                #pragma unroll
                for (int half_i = 0; half_i < 2; half_i++) {
                    size_t gi = (size_t)(r + half_i * 8) * HID + c;
                    float v0 = acc[mt][nt][half_i * 2 + 0];
                    float v1 = acc[mt][nt][half_i * 2 + 1];
                    float2 z2  = __half22float2(*(const __half2*)(g_z + gi));
                    float2 hv2 = *(const float2*)(h + gi);
                    float t0 = tanhf_fast(v0);
                    float t1 = tanhf_fast(v1);
                    float2 o;
                    o.x = hv2.x + z2.x * (t0 - hv2.x);
                    o.y = hv2.y + z2.y * (t1 - hv2.y);
                    *(float2*)(out + gi) = o;
                }
            }
        }
    }
}

// ---------------------------------------------------------------------------

extern "C" void kernel_launch(void* const* d_in, const int* in_sizes, int n_in,
                              void* d_out, int out_size)
{
    const float* h  = (const float*)d_in[0];
    const float* x  = (const float*)d_in[1];
    const float* Wr = (const float*)d_in[2];
    const float* Wz = (const float*)d_in[3];
    const float* Wh = (const float*)d_in[4];
    float* out = (float*)d_out;

    cudaFuncSetAttribute(gru_all, cudaFuncAttributeMaxDynamicSharedMemorySize, SMEM_TOTAL);

    init_kernel<<<1, 128>>>();
    prep_concat_kernel <<<2048, 256>>>(h, x);
    dim3 gT(HID / 32, KCAT / 32, 3);
    prep_weights_kernel<<<gT, dim3(32, 8)>>>(Wr, Wz, Wh);

    gru_all<<<NBLK, 256, SMEM_TOTAL>>>(h, out);
}